// round 17
// baseline (speedup 1.0000x reference)
#include <cuda_runtime.h>
#include <cuda_bf16.h>
#include <cstdint>
#include <math.h>

#define B_    4
#define S_    1024
#define DIM_  2048
#define NH_   32
#define NKV_  8
#define HD_   64
#define ASH_  3072     // (32 + 2*8) * 64
#define MTOT_ 4096     // B_ * S_
#define KDIM_ 2048

// ---- 3xBF16 GEMM tiling ----
#define STAGES   4
#define BM       128
#define BN       256
#define BK       16
#define NIT      (KDIM_ / BK)        // 128
#define RSTR     24                  // smem row stride in bf16 (48 B; 16 data + 8 pad)
#define AHI_OFF  0                   // bf16-unit offsets within a stage
#define ALO_OFF  (128 * RSTR)        // 3072
#define BHI_OFF  (256 * RSTR)        // 6144
#define BLO_OFF  (BHI_OFF + 256 * RSTR)  // 12288
#define STG_BF   (768 * RSTR)        // 18432 bf16 = 36864 B
#define STG_BYTES (STG_BF * 2)
#define SMEM_TOT (STAGES * STG_BYTES)  // 147456

// ---- flash attention smem layout (floats) ----
#define KPAD  68
#define VPAD  72
#define KS_F  (2 * 64 * KPAD)
#define VS_F  (2 * 64 * VPAD)
#define PS_F  (128 * KPAD)
#define ATTN_SMEM_B ((KS_F + VS_F + PS_F) * 4)  // 106496

// Scratch (allocation-free: __device__ globals)
__device__ float g_qkv[MTOT_ * ASH_];            // 48 MB (q/k/v tf32-rounded by rope)
__device__ __nv_bfloat16 g_xhi[MTOT_ * DIM_];    // 16 MB
__device__ __nv_bfloat16 g_xlo[MTOT_ * DIM_];    // 16 MB
__device__ __nv_bfloat16 g_whi[ASH_ * DIM_];     // 12 MB
__device__ __nv_bfloat16 g_wlo[ASH_ * DIM_];     // 12 MB
__device__ __nv_bfloat16 g_uhi[DIM_ * DIM_];     // 8 MB (wo)
__device__ __nv_bfloat16 g_ulo[DIM_ * DIM_];     // 8 MB
__device__ __nv_bfloat16 g_ohi[MTOT_ * DIM_];    // 16 MB (attn out)
__device__ __nv_bfloat16 g_olo[MTOT_ * DIM_];    // 16 MB

// ---------------------------------------------------------------------------
// PTX helpers
// ---------------------------------------------------------------------------
__device__ __forceinline__ uint32_t s2u(const void* p) {
  uint32_t a;
  asm("{ .reg .u64 t; cvta.to.shared.u64 t, %1; cvt.u32.u64 %0, t; }"
      : "=r"(a) : "l"(p));
  return a;
}
__device__ __forceinline__ float to_tf32(float x) {
  float y;
  asm("cvt.rna.tf32.f32 %0, %1;" : "=f"(y) : "f"(x));
  return y;
}
__device__ __forceinline__ void cpa16(uint32_t dst, const void* src) {
  asm volatile("cp.async.cg.shared.global [%0], [%1], 16;" :: "r"(dst), "l"(src));
}
__device__ __forceinline__ void cpa_commit() {
  asm volatile("cp.async.commit_group;" ::: "memory");
}
template <int N>
__device__ __forceinline__ void cpa_wait() {
  asm volatile("cp.async.wait_group %0;" :: "n"(N) : "memory");
}
__device__ __forceinline__ void mma_tf32_16x8x8(float* d, const uint32_t* a,
                                                const uint32_t* b) {
  asm volatile(
      "mma.sync.aligned.m16n8k8.row.col.f32.tf32.tf32.f32 "
      "{%0,%1,%2,%3}, {%4,%5,%6,%7}, {%8,%9}, {%0,%1,%2,%3};\n"
      : "+f"(d[0]), "+f"(d[1]), "+f"(d[2]), "+f"(d[3])
      : "r"(a[0]), "r"(a[1]), "r"(a[2]), "r"(a[3]), "r"(b[0]), "r"(b[1]));
}
__device__ __forceinline__ void mma_bf16_16x8x16(float* d, uint32_t a0,
                                                 uint32_t a1, uint32_t a2,
                                                 uint32_t a3, uint32_t b0,
                                                 uint32_t b1) {
  asm volatile(
      "mma.sync.aligned.m16n8k16.row.col.f32.bf16.bf16.f32 "
      "{%0,%1,%2,%3}, {%4,%5,%6,%7}, {%8,%9}, {%0,%1,%2,%3};\n"
      : "+f"(d[0]), "+f"(d[1]), "+f"(d[2]), "+f"(d[3])
      : "r"(a0), "r"(a1), "r"(a2), "r"(a3), "r"(b0), "r"(b1));
}

// ---------------------------------------------------------------------------
// Split fp32 -> (hi, lo) bf16, k16-permuted: [0,1,8,9,2,3,10,11,4,5,12,13,6,7,14,15]
// so bf16 mma fragments are contiguous 8B (LDS.64 per fragment pair).
// One thread = one 16-element k-group.
// ---------------------------------------------------------------------------
__global__ void split_bf16_kernel(const float* __restrict__ src,
                                  __nv_bfloat16* __restrict__ hi,
                                  __nv_bfloat16* __restrict__ lo, int n16) {
  int i = blockIdx.x * blockDim.x + threadIdx.x;
  if (i >= n16) return;
  const float4* s = (const float4*)src + (size_t)i * 4;
  float4 f0 = s[0], f1 = s[1], f2 = s[2], f3 = s[3];
  float v[16] = {f0.x, f0.y, f2.x, f2.y, f0.z, f0.w, f2.z, f2.w,
                 f1.x, f1.y, f3.x, f3.y, f1.z, f1.w, f3.z, f3.w};
  uint32_t ho[8], lu[8];
#pragma unroll
  for (int p = 0; p < 8; p++) {
    __nv_bfloat16 h0 = __float2bfloat16(v[2 * p]);
    __nv_bfloat16 h1 = __float2bfloat16(v[2 * p + 1]);
    __nv_bfloat16 l0 = __float2bfloat16(v[2 * p] - __bfloat162float(h0));
    __nv_bfloat16 l1 = __float2bfloat16(v[2 * p + 1] - __bfloat162float(h1));
    __nv_bfloat162 hh; hh.x = h0; hh.y = h1;
    __nv_bfloat162 ll; ll.x = l0; ll.y = l1;
    ho[p] = *(uint32_t*)&hh;
    lu[p] = *(uint32_t*)&ll;
  }
  uint4* hd = (uint4*)(hi + (size_t)i * 16);
  uint4* ld = (uint4*)(lo + (size_t)i * 16);
  hd[0] = make_uint4(ho[0], ho[1], ho[2], ho[3]);
  hd[1] = make_uint4(ho[4], ho[5], ho[6], ho[7]);
  ld[0] = make_uint4(lu[0], lu[1], lu[2], lu[3]);
  ld[1] = make_uint4(lu[4], lu[5], lu[6], lu[7]);
}

// ---------------------------------------------------------------------------
// 3xBF16 GEMM (NT): C = (Ahi+Alo)(Bhi+Blo)^T dropping AloBlo.
// 128x256 block, BK=16, 8 warps (2M x 4N), warp tile 64x64.
// Per k16 per warp: 32 LDS.64 + 96 full-rate bf16 MMAs.
// ---------------------------------------------------------------------------
__global__ __launch_bounds__(256) void gemm_bf16x3(
    const __nv_bfloat16* __restrict__ Ahi, const __nv_bfloat16* __restrict__ Alo,
    const __nv_bfloat16* __restrict__ Bhi, const __nv_bfloat16* __restrict__ Blo,
    float* __restrict__ C, int Ntot) {
  extern __shared__ __nv_bfloat16 smh[];
  const uint32_t sb = s2u(smh);
  const int tid = threadIdx.x, wid = tid >> 5, lid = tid & 31;
  const int wm = wid & 1, wn = wid >> 1;
  const int r = lid >> 2, cc = lid & 3;
  const int m0 = blockIdx.y * BM, n0 = blockIdx.x * BN;

  auto load_tile = [&](int i) {
    uint32_t st = sb + (i % STAGES) * STG_BYTES;
    int k0 = i * BK;
#pragma unroll
    for (int c = 0; c < 2; c++) {  // A: 512 chunks (hi+lo)
      int ch = tid + c * 256;
      int hl = ch >> 8, rem = ch & 255, row = rem >> 1, half = rem & 1;
      const __nv_bfloat16* sa = hl ? Alo : Ahi;
      cpa16(st + (uint32_t)(hl * (ALO_OFF * 2) + row * (RSTR * 2) + half * 16),
            sa + (size_t)(m0 + row) * KDIM_ + k0 + half * 8);
    }
#pragma unroll
    for (int c = 0; c < 4; c++) {  // B: 1024 chunks (hi+lo)
      int ch = tid + c * 256;
      int hl = ch >> 9, rem = ch & 511, row = rem >> 1, half = rem & 1;
      const __nv_bfloat16* sbp = hl ? Blo : Bhi;
      cpa16(st + (uint32_t)(BHI_OFF * 2 + hl * (256 * RSTR * 2) +
                            row * (RSTR * 2) + half * 16),
            sbp + (size_t)(n0 + row) * KDIM_ + k0 + half * 8);
    }
  };

  float acc[4][8][4];
#pragma unroll
  for (int mt = 0; mt < 4; mt++)
#pragma unroll
    for (int nt = 0; nt < 8; nt++)
#pragma unroll
      for (int q = 0; q < 4; q++) acc[mt][nt][q] = 0.f;

#pragma unroll
  for (int i = 0; i < STAGES - 1; i++) { load_tile(i); cpa_commit(); }

  for (int i = 0; i < NIT; i++) {
    int s = i % STAGES;
    cpa_wait<STAGES - 2>();
    __syncthreads();

    int j = i + STAGES - 1;
    if (j < NIT) { load_tile(j); cpa_commit(); }

    const __nv_bfloat16* Ss = smh + s * STG_BF;
    const __nv_bfloat16* Ah = Ss + AHI_OFF;
    const __nv_bfloat16* Al = Ss + ALO_OFF;
    const __nv_bfloat16* Bh = Ss + BHI_OFF;
    const __nv_bfloat16* Bl = Ss + BLO_OFF;

    uint2 ah[4][2], bh[8];
#pragma unroll
    for (int mt = 0; mt < 4; mt++) {
      int base = (wm * 64 + mt * 16 + r) * RSTR + cc * 4;
      ah[mt][0] = *(const uint2*)(Ah + base);
      ah[mt][1] = *(const uint2*)(Ah + base + 8 * RSTR);
    }
#pragma unroll
    for (int nt = 0; nt < 8; nt++)
      bh[nt] = *(const uint2*)(Bh + (wn * 64 + nt * 8 + r) * RSTR + cc * 4);

    // pass 1: Ahi * Bhi
#pragma unroll
    for (int mt = 0; mt < 4; mt++)
#pragma unroll
      for (int nt = 0; nt < 8; nt++)
        mma_bf16_16x8x16(acc[mt][nt], ah[mt][0].x, ah[mt][1].x, ah[mt][0].y,
                         ah[mt][1].y, bh[nt].x, bh[nt].y);

    // pass 2: Alo * Bhi
    uint2 al[4][2];
#pragma unroll
    for (int mt = 0; mt < 4; mt++) {
      int base = (wm * 64 + mt * 16 + r) * RSTR + cc * 4;
      al[mt][0] = *(const uint2*)(Al + base);
      al[mt][1] = *(const uint2*)(Al + base + 8 * RSTR);
    }
#pragma unroll
    for (int mt = 0; mt < 4; mt++)
#pragma unroll
      for (int nt = 0; nt < 8; nt++)
        mma_bf16_16x8x16(acc[mt][nt], al[mt][0].x, al[mt][1].x, al[mt][0].y,
                         al[mt][1].y, bh[nt].x, bh[nt].y);

    // pass 3: Ahi * Blo
    uint2 bl[8];
#pragma unroll
    for (int nt = 0; nt < 8; nt++)
      bl[nt] = *(const uint2*)(Bl + (wn * 64 + nt * 8 + r) * RSTR + cc * 4);
#pragma unroll
    for (int mt = 0; mt < 4; mt++)
#pragma unroll
      for (int nt = 0; nt < 8; nt++)
        mma_bf16_16x8x16(acc[mt][nt], ah[mt][0].x, ah[mt][1].x, ah[mt][0].y,
                         ah[mt][1].y, bl[nt].x, bl[nt].y);
  }

  // epilogue (same output mapping as m16n8k8)
#pragma unroll
  for (int mt = 0; mt < 4; mt++) {
    int row0 = m0 + wm * 64 + mt * 16 + r;
#pragma unroll
    for (int nt = 0; nt < 8; nt++) {
      int col = n0 + wn * 64 + nt * 8 + cc * 2;
      float2 v01 = {acc[mt][nt][0], acc[mt][nt][1]};
      float2 v23 = {acc[mt][nt][2], acc[mt][nt][3]};
      *(float2*)(C + (size_t)row0 * Ntot + col) = v01;
      *(float2*)(C + (size_t)(row0 + 8) * Ntot + col) = v23;
    }
  }
}

// ---------------------------------------------------------------------------
// RoPE in-place on q (slots 0..3) and k (slot 4); v (slot 5) rounding only.
// ALL outputs tf32-rounded so flash_mma needs no cvt on Q/K/V.
// ---------------------------------------------------------------------------
__global__ void rope_kernel(float* __restrict__ qkv,
                            const float* __restrict__ cs,
                            const float* __restrict__ sn) {
  int p = blockIdx.x * blockDim.x + threadIdx.x;
  if (p >= MTOT_ * 48 * 32) return;
  int i = p & 31;
  int hh = (p >> 5) % 48;
  int m = p / (48 * 32);
  int s = m & (S_ - 1);
  int g = hh / 6, j = hh - g * 6;
  size_t base = (size_t)m * ASH_ + g * 384 + j * 64 + 2 * i;
  float2 v = *(float2*)(qkv + base);
  float2 o;
  if (j < 5) {
    float c = cs[s * 32 + i], si = sn[s * 32 + i];
    o.x = to_tf32(v.x * c - v.y * si);
    o.y = to_tf32(v.x * si + v.y * c);
  } else {
    o.x = to_tf32(v.x);
    o.y = to_tf32(v.y);
  }
  *(float2*)(qkv + base) = o;
}

// ---------------------------------------------------------------------------
// Tensor-core flash attention (causal, GQA), tf32 mma.sync.
// Epilogue emits hi/lo bf16, k16-permuted, as operand A of the out-proj.
// ---------------------------------------------------------------------------
__global__ __launch_bounds__(256) void flash_mma(
    const float* __restrict__ qkv, __nv_bfloat16* __restrict__ ohi,
    __nv_bfloat16* __restrict__ olo) {
  extern __shared__ float smf[];
  float* Ksm = smf;
  float* Vsm = smf + KS_F;
  float* Psm = smf + KS_F + VS_F;
  const uint32_t sb = s2u(smf);
  const uint32_t ks_b = sb;
  const uint32_t vs_b = sb + KS_F * 4;

  const int qt = blockIdx.x, h = blockIdx.y, b = blockIdx.z;
  const int g = h >> 2;
  const float* qb = qkv + (size_t)b * S_ * ASH_ + g * 384 + (h & 3) * 64;
  const float* kb = qkv + (size_t)b * S_ * ASH_ + g * 384 + 256;
  const int tid = threadIdx.x, wid = tid >> 5, lid = tid & 31;
  const int r = lid >> 2, cc = lid & 3;
  const int r0 = qt * 128;
  const int wrow = wid * 16;

  auto load_kv = [&](int kt, int st) {
#pragma unroll
    for (int c = 0; c < 4; c++) {
      int ch = tid + c * 256;
      int key = ch >> 4, d4 = ch & 15;
      const float* src = kb + (size_t)(kt * 64 + key) * ASH_ + d4 * 4;
      cpa16(ks_b + (uint32_t)(st * 64 * KPAD * 4 + key * (KPAD * 4) + d4 * 16),
            src);
      cpa16(vs_b + (uint32_t)(st * 64 * VPAD * 4 + key * (VPAD * 4) + d4 * 16),
            src + 64);
    }
  };

  uint32_t qf[8][4];
  {
    const float* q0 = qb + (size_t)(r0 + wrow + r) * ASH_;
    const float* q1 = q0 + 8 * ASH_;
#pragma unroll
    for (int ks = 0; ks < 8; ks++) {
      qf[ks][0] = __float_as_uint(0.125f * __ldg(q0 + ks * 8 + cc));
      qf[ks][1] = __float_as_uint(0.125f * __ldg(q1 + ks * 8 + cc));
      qf[ks][2] = __float_as_uint(0.125f * __ldg(q0 + ks * 8 + cc + 4));
      qf[ks][3] = __float_as_uint(0.125f * __ldg(q1 + ks * 8 + cc + 4));
    }
  }

  float m0r = -1e30f, m1r = -1e30f, l0 = 0.f, l1 = 0.f;
  float Oa[8][4];
#pragma unroll
  for (int nt = 0; nt < 8; nt++)
#pragma unroll
    for (int q = 0; q < 4; q++) Oa[nt][q] = 0.f;

  const int nkt = 2 * qt + 2;
  load_kv(0, 0);
  cpa_commit();

  for (int kt = 0; kt < nkt; kt++) {
    const int st = kt & 1;
    if (kt + 1 < nkt) {
      load_kv(kt + 1, st ^ 1);
      cpa_commit();
      cpa_wait<1>();
    } else {
      cpa_wait<0>();
    }
    __syncthreads();

    const float* Kt = Ksm + st * 64 * KPAD;
    const float* Vt = Vsm + st * 64 * VPAD;

    float Sa[8][4];
#pragma unroll
    for (int nt = 0; nt < 8; nt++)
#pragma unroll
      for (int q = 0; q < 4; q++) Sa[nt][q] = 0.f;
#pragma unroll
    for (int ks = 0; ks < 8; ks++) {
      uint32_t bf[8][2];
#pragma unroll
      for (int nt = 0; nt < 8; nt++) {
        const float* kp = Kt + (nt * 8 + r) * KPAD + ks * 8 + cc;
        bf[nt][0] = __float_as_uint(kp[0]);
        bf[nt][1] = __float_as_uint(kp[4]);
      }
#pragma unroll
      for (int nt = 0; nt < 8; nt++)
        mma_tf32_16x8x8(Sa[nt], qf[ks], bf[nt]);
    }

    if (kt >= 2 * qt) {
      const int row_a = r0 + wrow + r, row_b = row_a + 8;
#pragma unroll
      for (int nt = 0; nt < 8; nt++) {
        int col = kt * 64 + nt * 8 + 2 * cc;
        if (col > row_a) Sa[nt][0] = -1e30f;
        if (col + 1 > row_a) Sa[nt][1] = -1e30f;
        if (col > row_b) Sa[nt][2] = -1e30f;
        if (col + 1 > row_b) Sa[nt][3] = -1e30f;
      }
    }

    float mx0 = -1e30f, mx1 = -1e30f;
#pragma unroll
    for (int nt = 0; nt < 8; nt++) {
      mx0 = fmaxf(mx0, fmaxf(Sa[nt][0], Sa[nt][1]));
      mx1 = fmaxf(mx1, fmaxf(Sa[nt][2], Sa[nt][3]));
    }
#pragma unroll
    for (int d = 1; d <= 2; d <<= 1) {
      mx0 = fmaxf(mx0, __shfl_xor_sync(0xffffffffu, mx0, d));
      mx1 = fmaxf(mx1, __shfl_xor_sync(0xffffffffu, mx1, d));
    }
    float mn0 = fmaxf(m0r, mx0), mn1 = fmaxf(m1r, mx1);
    float al0 = __expf(m0r - mn0), al1 = __expf(m1r - mn1);
    m0r = mn0; m1r = mn1;
    float s0 = 0.f, s1 = 0.f;
#pragma unroll
    for (int nt = 0; nt < 8; nt++) {
      Sa[nt][0] = __expf(Sa[nt][0] - mn0); s0 += Sa[nt][0];
      Sa[nt][1] = __expf(Sa[nt][1] - mn0); s0 += Sa[nt][1];
      Sa[nt][2] = __expf(Sa[nt][2] - mn1); s1 += Sa[nt][2];
      Sa[nt][3] = __expf(Sa[nt][3] - mn1); s1 += Sa[nt][3];
    }
#pragma unroll
    for (int d = 1; d <= 2; d <<= 1) {
      s0 += __shfl_xor_sync(0xffffffffu, s0, d);
      s1 += __shfl_xor_sync(0xffffffffu, s1, d);
    }
    l0 = l0 * al0 + s0;
    l1 = l1 * al1 + s1;
#pragma unroll
    for (int nt = 0; nt < 8; nt++) {
      Oa[nt][0] *= al0; Oa[nt][1] *= al0;
      Oa[nt][2] *= al1; Oa[nt][3] *= al1;
    }

    {
      float* pr = Psm + (wrow + r) * KPAD;
#pragma unroll
      for (int nt = 0; nt < 8; nt++) {
        float2 p01 = {to_tf32(Sa[nt][0]), to_tf32(Sa[nt][1])};
        float2 p23 = {to_tf32(Sa[nt][2]), to_tf32(Sa[nt][3])};
        *(float2*)(pr + nt * 8 + 2 * cc) = p01;
        *(float2*)(pr + 8 * KPAD + nt * 8 + 2 * cc) = p23;
      }
    }
    __syncwarp();

#pragma unroll
    for (int ks = 0; ks < 8; ks++) {
      uint32_t pf[4];
      const float* pp = Psm + (wrow + r) * KPAD + ks * 8 + cc;
      pf[0] = __float_as_uint(pp[0]);
      pf[1] = __float_as_uint(pp[8 * KPAD]);
      pf[2] = __float_as_uint(pp[4]);
      pf[3] = __float_as_uint(pp[8 * KPAD + 4]);
      uint32_t vf[8][2];
#pragma unroll
      for (int nt = 0; nt < 8; nt++) {
        const float* vp = Vt + (ks * 8 + cc) * VPAD + nt * 8 + r;
        vf[nt][0] = __float_as_uint(vp[0]);
        vf[nt][1] = __float_as_uint(vp[4 * VPAD]);
      }
#pragma unroll
      for (int nt = 0; nt < 8; nt++)
        mma_tf32_16x8x8(Oa[nt], pf, vf[nt]);
    }
    __syncthreads();
  }

  // epilogue: normalize, split to hi/lo bf16, store k16-PERMUTED.
  // within-k16 pair index p = 4*(nt&1)+cc -> position 4*cc + 2*(nt&1).
  const float inv0 = 1.f / l0, inv1 = 1.f / l1;
  const size_t ro = (size_t)(b * S_ + r0 + wrow + r) * DIM_;
#pragma unroll
  for (int nt = 0; nt < 8; nt++) {
    int cidx = h * 64 + (nt >> 1) * 16 + 4 * cc + 2 * (nt & 1);
#pragma unroll
    for (int half = 0; half < 2; half++) {
      float v0 = Oa[nt][2 * half + 0] * (half ? inv1 : inv0);
      float v1 = Oa[nt][2 * half + 1] * (half ? inv1 : inv0);
      __nv_bfloat16 h0 = __float2bfloat16(v0);
      __nv_bfloat16 h1 = __float2bfloat16(v1);
      __nv_bfloat16 e0 = __float2bfloat16(v0 - __bfloat162float(h0));
      __nv_bfloat16 e1 = __float2bfloat16(v1 - __bfloat162float(h1));
      __nv_bfloat162 hh; hh.x = h0; hh.y = h1;
      __nv_bfloat162 ee; ee.x = e0; ee.y = e1;
      size_t off = ro + (size_t)half * 8 * DIM_ + cidx;
      *(__nv_bfloat162*)(ohi + off) = hh;
      *(__nv_bfloat162*)(olo + off) = ee;
    }
  }
}

// ---------------------------------------------------------------------------
extern "C" void kernel_launch(void* const* d_in, const int* in_sizes, int n_in,
                              void* d_out, int out_size) {
  const float* x    = (const float*)d_in[0];
  const float* fc   = (const float*)d_in[1];
  const float* fs   = (const float*)d_in[2];
  const float* wqkv = (const float*)d_in[3];
  const float* wo   = (const float*)d_in[4];
  float* out = (float*)d_out;

  float* qkv_p;
  __nv_bfloat16 *xhi, *xlo, *whi, *wlo, *uhi, *ulo, *ohi, *olo;
  cudaGetSymbolAddress((void**)&qkv_p, g_qkv);
  cudaGetSymbolAddress((void**)&xhi, g_xhi);
  cudaGetSymbolAddress((void**)&xlo, g_xlo);
  cudaGetSymbolAddress((void**)&whi, g_whi);
  cudaGetSymbolAddress((void**)&wlo, g_wlo);
  cudaGetSymbolAddress((void**)&uhi, g_uhi);
  cudaGetSymbolAddress((void**)&ulo, g_ulo);
  cudaGetSymbolAddress((void**)&ohi, g_ohi);
  cudaGetSymbolAddress((void**)&olo, g_olo);

  cudaFuncSetAttribute(gemm_bf16x3, cudaFuncAttributeMaxDynamicSharedMemorySize,
                       SMEM_TOT);
  cudaFuncSetAttribute(flash_mma, cudaFuncAttributeMaxDynamicSharedMemorySize,
                       ATTN_SMEM_B);

  // 0) split operands into hi/lo bf16 (k16-permuted)
  {
    int n16 = MTOT_ * DIM_ / 16;
    split_bf16_kernel<<<(n16 + 255) / 256, 256>>>(x, xhi, xlo, n16);
    n16 = ASH_ * DIM_ / 16;
    split_bf16_kernel<<<(n16 + 255) / 256, 256>>>(wqkv, whi, wlo, n16);
    n16 = DIM_ * DIM_ / 16;
    split_bf16_kernel<<<(n16 + 255) / 256, 256>>>(wo, uhi, ulo, n16);
  }

  // 1) QKV projection (3xbf16)
  gemm_bf16x3<<<dim3(ASH_ / BN, MTOT_ / BM), 256, SMEM_TOT>>>(
      xhi, xlo, whi, wlo, qkv_p, ASH_);

  // 2) RoPE (+ tf32 rounding of q/k/v)
  {
    int total = MTOT_ * 48 * 32;
    rope_kernel<<<(total + 255) / 256, 256>>>(qkv_p, fc, fs);
  }

  // 3) causal GQA flash attention (tf32), emits hi/lo bf16 output
  flash_mma<<<dim3(S_ / 128, NH_, B_), 256, ATTN_SMEM_B>>>(qkv_p, ohi, olo);

  // 4) output projection (3xbf16)
  gemm_bf16x3<<<dim3(DIM_ / BN, MTOT_ / BM), 256, SMEM_TOT>>>(
      ohi, olo, uhi, ulo, out, DIM_);
}